// round 2
// baseline (speedup 1.0000x reference)
#include <cuda_runtime.h>
#include <math.h>

// Problem constants
#define BB   4
#define LLEN 2048
#define DM   1024
#define DC   512
#define DI   1024
#define NS   16
#define DTRC 32
#define NROWS (BB*LLEN)   // 8192

// ---------------- scratch (allocated at module load, allowed) ----------------
__device__ float g_s    [NROWS*DM];       // LayerNorm output s
__device__ float g_h    [NROWS*DC];       // residual stream h
__device__ float g_xn   [NROWS*DC];       // rmsnorm(h)
__device__ float g_xz   [NROWS*2*DI];     // in_proj output [xc | z]
__device__ float g_xc   [NROWS*DI];       // conv+silu output
__device__ float g_dbc  [NROWS*64];       // x_proj output [dt(32) | B(16) | C(16)]
__device__ float g_delta[NROWS*DI];       // softplus(dt@dtW+dtb)
__device__ float g_y    [NROWS*DI];       // scan output * silu(z)
__device__ float g_out  [NROWS*DM];       // concat(x1, x2+h)

// ---------------- helpers ----------------
__device__ __forceinline__ float softplusf(float x) {
    return (x > 20.f) ? x : log1pf(expf(x));
}
__device__ __forceinline__ float siluf(float x) {
    return x / (1.f + __expf(-x));
}

// ---------------- LayerNorm: src -> g_s ; also init g_h = s[:, :512] ----------------
__global__ void layernorm_kernel(const float* __restrict__ src,
                                 const float* __restrict__ gma,
                                 const float* __restrict__ bta)
{
    int row = blockIdx.x;
    int t = threadIdx.x;                       // 256 threads, 4 elems each
    const float4* x4 = (const float4*)(src + (size_t)row * DM);
    float4 v = x4[t];
    float sum = v.x + v.y + v.z + v.w;
    float sq  = v.x*v.x + v.y*v.y + v.z*v.z + v.w*v.w;
    #pragma unroll
    for (int o = 16; o > 0; o >>= 1) {
        sum += __shfl_down_sync(0xffffffffu, sum, o);
        sq  += __shfl_down_sync(0xffffffffu, sq,  o);
    }
    __shared__ float sm[18];
    int w = t >> 5;
    if ((t & 31) == 0) { sm[w] = sum; sm[8 + w] = sq; }
    __syncthreads();
    if (t == 0) {
        float s1 = 0.f, s2 = 0.f;
        #pragma unroll
        for (int i = 0; i < 8; i++) { s1 += sm[i]; s2 += sm[8 + i]; }
        float mu  = s1 * (1.f / DM);
        float var = s2 * (1.f / DM) - mu * mu;
        sm[16] = mu;
        sm[17] = rsqrtf(var + 1e-5f);
    }
    __syncthreads();
    float mu = sm[16], inv = sm[17];
    float4 gv = ((const float4*)gma)[t];
    float4 bv = ((const float4*)bta)[t];
    float4 o;
    o.x = (v.x - mu) * inv * gv.x + bv.x;
    o.y = (v.y - mu) * inv * gv.y + bv.y;
    o.z = (v.z - mu) * inv * gv.z + bv.z;
    o.w = (v.w - mu) * inv * gv.w + bv.w;
    ((float4*)(g_s + (size_t)row * DM))[t] = o;
    if (t < DC / 4) ((float4*)(g_h + (size_t)row * DC))[t] = o;
}

// ---------------- RMSNorm: g_h -> g_xn ----------------
__global__ void rmsnorm_kernel(const float* __restrict__ wptr)
{
    int row = blockIdx.x;
    int t = threadIdx.x;                       // 128 threads, 4 elems each
    float4 v = ((const float4*)(g_h + (size_t)row * DC))[t];
    float sq = v.x*v.x + v.y*v.y + v.z*v.z + v.w*v.w;
    #pragma unroll
    for (int o = 16; o > 0; o >>= 1) sq += __shfl_down_sync(0xffffffffu, sq, o);
    __shared__ float sm[5];
    int w = t >> 5;
    if ((t & 31) == 0) sm[w] = sq;
    __syncthreads();
    if (t == 0) {
        float s2 = sm[0] + sm[1] + sm[2] + sm[3];
        sm[4] = rsqrtf(s2 * (1.f / DC) + 1e-5f);
    }
    __syncthreads();
    float inv = sm[4];
    float4 wv = ((const float4*)wptr)[t];
    float4 o;
    o.x = v.x * inv * wv.x;
    o.y = v.y * inv * wv.y;
    o.z = v.z * inv * wv.z;
    o.w = v.w * inv * wv.w;
    ((float4*)(g_xn + (size_t)row * DC))[t] = o;
}

// ---------------- generic SGEMM: C[M,N] = A[M,K] @ B[N,K]^T (+ epilogues) ----------------
// EPI 0: C = acc
// EPI 1: C = softplus(acc + bias[col])
// EPI 2: C += acc
// EPI 3: C = addsrc[row,col] + acc + bias[col]
#define BM 128
#define BN 64
#define BK 16

template<int EPI>
__global__ void __launch_bounds__(256)
sgemm_kernel(const float* __restrict__ A, const float* __restrict__ B,
             float* __restrict__ C, int M, int N, int K,
             int lda, int ldb, int ldc,
             const float* __restrict__ bias, const float* __restrict__ addsrc)
{
    __shared__ float As[BK][BM + 4];
    __shared__ float Bs[BK][BN + 4];
    const int tid = threadIdx.x;
    const int bm = blockIdx.y * BM;
    const int bn = blockIdx.x * BN;
    const int tx = tid & 15;   // n-dir, 4 cols each
    const int ty = tid >> 4;   // m-dir, 8 rows each
    float acc[8][4];
    #pragma unroll
    for (int i = 0; i < 8; i++)
        #pragma unroll
        for (int j = 0; j < 4; j++) acc[i][j] = 0.f;

    const int lm = tid >> 2;          // 0..63
    const int lk = (tid & 3) << 2;    // 0,4,8,12
    const float* Ap0 = A + (size_t)(bm + lm)      * lda + lk;
    const float* Ap1 = A + (size_t)(bm + lm + 64) * lda + lk;
    const float* Bp  = B + (size_t)(bn + lm)      * ldb + lk;

    for (int k0 = 0; k0 < K; k0 += BK) {
        float4 a0 = *(const float4*)(Ap0 + k0);
        float4 a1 = *(const float4*)(Ap1 + k0);
        float4 bv = *(const float4*)(Bp  + k0);
        As[lk + 0][lm] = a0.x; As[lk + 1][lm] = a0.y;
        As[lk + 2][lm] = a0.z; As[lk + 3][lm] = a0.w;
        As[lk + 0][lm + 64] = a1.x; As[lk + 1][lm + 64] = a1.y;
        As[lk + 2][lm + 64] = a1.z; As[lk + 3][lm + 64] = a1.w;
        Bs[lk + 0][lm] = bv.x; Bs[lk + 1][lm] = bv.y;
        Bs[lk + 2][lm] = bv.z; Bs[lk + 3][lm] = bv.w;
        __syncthreads();
        #pragma unroll
        for (int kk = 0; kk < BK; kk++) {
            float4 alo = *(const float4*)&As[kk][ty * 8];
            float4 ahi = *(const float4*)&As[kk][ty * 8 + 4];
            float4 b   = *(const float4*)&Bs[kk][tx * 4];
            float av[8] = {alo.x, alo.y, alo.z, alo.w, ahi.x, ahi.y, ahi.z, ahi.w};
            float bw[4] = {b.x, b.y, b.z, b.w};
            #pragma unroll
            for (int i = 0; i < 8; i++)
                #pragma unroll
                for (int j = 0; j < 4; j++)
                    acc[i][j] = fmaf(av[i], bw[j], acc[i][j]);
        }
        __syncthreads();
    }

    #pragma unroll
    for (int i = 0; i < 8; i++) {
        int row = bm + ty * 8 + i;
        #pragma unroll
        for (int j = 0; j < 4; j++) {
            int col = bn + tx * 4 + j;
            size_t ci = (size_t)row * ldc + col;
            float v = acc[i][j];
            if (EPI == 0) {
                C[ci] = v;
            } else if (EPI == 1) {
                C[ci] = softplusf(v + bias[col]);
            } else if (EPI == 2) {
                C[ci] += v;
            } else {
                C[ci] = addsrc[ci] + v + bias[col];
            }
        }
    }
}

// ---------------- depthwise causal conv (DCONV=4) + bias + silu: g_xz[:, :DI] -> g_xc ----------------
__global__ void conv_kernel(const float* __restrict__ cw, const float* __restrict__ cb)
{
    int idx = blockIdx.x * blockDim.x + threadIdx.x;
    if (idx >= NROWS * DI) return;
    int d   = idx & (DI - 1);
    int row = idx >> 10;          // b*L + l
    int l   = row & (LLEN - 1);
    float w0 = cw[d * 4 + 0], w1 = cw[d * 4 + 1], w2 = cw[d * 4 + 2], w3 = cw[d * 4 + 3];
    float acc = cb[d];
    if (l >= 3) acc = fmaf(w0, g_xz[(size_t)(row - 3) * (2 * DI) + d], acc);
    if (l >= 2) acc = fmaf(w1, g_xz[(size_t)(row - 2) * (2 * DI) + d], acc);
    if (l >= 1) acc = fmaf(w2, g_xz[(size_t)(row - 1) * (2 * DI) + d], acc);
    acc = fmaf(w3, g_xz[(size_t)row * (2 * DI) + d], acc);
    g_xc[idx] = siluf(acc);
}

// ---------------- selective scan ----------------
// One thread per (b, d, n). Warp = 2 d-channels x 16 n-states.
// y[b,l,d] = (sum_n h*C + Dp[d]*xc) * silu(z)
__global__ void scan_kernel(const float* __restrict__ A_log, const float* __restrict__ Dp)
{
    int b     = blockIdx.x >> 6;          // DI/16 = 64 blocks per batch
    int dbase = (blockIdx.x & 63) << 4;
    int warp  = threadIdx.x >> 5;         // 8 warps
    int lane  = threadIdx.x & 31;
    int g     = lane >> 4;
    int n     = lane & 15;
    int d     = dbase + warp * 2 + g;

    float An  = -__expf(A_log[d * NS + n]);
    float Dpd = Dp[d];
    float h = 0.f;
    size_t rowBase = (size_t)b * LLEN;

    for (int l = 0; l < LLEN; l++) {
        size_t r = rowBase + l;
        float dv = g_delta[r * DI + d];
        float xv = g_xc[r * DI + d];
        float Bn = g_dbc[r * 64 + 32 + n];
        float Cn = g_dbc[r * 64 + 48 + n];
        float a  = __expf(dv * An);
        h = fmaf(a, h, dv * xv * Bn);
        float contrib = h * Cn;
        contrib += __shfl_xor_sync(0xffffffffu, contrib, 8);
        contrib += __shfl_xor_sync(0xffffffffu, contrib, 4);
        contrib += __shfl_xor_sync(0xffffffffu, contrib, 2);
        contrib += __shfl_xor_sync(0xffffffffu, contrib, 1);
        if (n == 0) {
            float zv = g_xz[r * (2 * DI) + DI + d];
            g_y[r * DI + d] = (contrib + Dpd * xv) * siluf(zv);
        }
    }
}

// ---------------- build out = concat(x1, x2 + h) ----------------
__global__ void buildout_kernel()
{
    int idx = blockIdx.x * blockDim.x + threadIdx.x;
    if (idx >= NROWS * DM) return;
    int c   = idx & (DM - 1);
    int row = idx >> 10;
    float v = g_s[idx];
    if (c >= DC) v += g_h[(size_t)row * DC + (c - DC)];
    g_out[idx] = v;
}

// ---------------- launch ----------------
extern "C" void kernel_launch(void* const* d_in, const int* in_sizes, int n_in,
                              void* d_out, int out_size)
{
    const float* src    = (const float*)d_in[0];
    const float* ln_g   = (const float*)d_in[1];
    const float* ln_b   = (const float*)d_in[2];
    const float* po_W   = (const float*)d_in[3];
    const float* po_b   = (const float*)d_in[4];
    const float* rms_w  = (const float*)d_in[5];
    const float* in_W   = (const float*)d_in[6];
    const float* conv_w = (const float*)d_in[7];
    const float* conv_b = (const float*)d_in[8];
    const float* xp_W   = (const float*)d_in[9];
    const float* dt_W   = (const float*)d_in[10];
    const float* dt_b   = (const float*)d_in[11];
    const float* A_log  = (const float*)d_in[12];
    const float* Dp     = (const float*)d_in[13];
    const float* mo_W   = (const float*)d_in[14];

    float *ps, *pxn, *pxz, *pxc, *pdbc, *pdelta, *py, *ph, *pout;
    cudaGetSymbolAddress((void**)&ps,     g_s);
    cudaGetSymbolAddress((void**)&ph,     g_h);
    cudaGetSymbolAddress((void**)&pxn,    g_xn);
    cudaGetSymbolAddress((void**)&pxz,    g_xz);
    cudaGetSymbolAddress((void**)&pxc,    g_xc);
    cudaGetSymbolAddress((void**)&pdbc,   g_dbc);
    cudaGetSymbolAddress((void**)&pdelta, g_delta);
    cudaGetSymbolAddress((void**)&py,     g_y);
    cudaGetSymbolAddress((void**)&pout,   g_out);

    layernorm_kernel<<<NROWS, 256>>>(src, ln_g, ln_b);

    for (int i = 0; i < 2; i++) {
        rmsnorm_kernel<<<NROWS, 128>>>(rms_w + i * DC);
        // xz = xn @ in_W[i]^T     (8192 x 2048 x 512)
        sgemm_kernel<0><<<dim3((2 * DI) / BN, NROWS / BM), 256>>>(
            pxn, in_W + (size_t)i * 2 * DI * DC, pxz,
            NROWS, 2 * DI, DC, DC, DC, 2 * DI, nullptr, nullptr);
        // depthwise conv + silu
        conv_kernel<<<(NROWS * DI) / 256, 256>>>(conv_w + (size_t)i * DI * 4, conv_b + (size_t)i * DI);
        // dbc = xc @ xp_W[i]^T    (8192 x 64 x 1024)
        sgemm_kernel<0><<<dim3(64 / BN, NROWS / BM), 256>>>(
            pxc, xp_W + (size_t)i * 64 * DI, pdbc,
            NROWS, 64, DI, DI, DI, 64, nullptr, nullptr);
        // delta = softplus(dt @ dt_W[i]^T + dt_b)   (8192 x 1024 x 32), dt = dbc[:, :32] (lda=64)
        sgemm_kernel<1><<<dim3(DI / BN, NROWS / BM), 256>>>(
            pdbc, dt_W + (size_t)i * DI * DTRC, pdelta,
            NROWS, DI, DTRC, 64, DTRC, DI, dt_b + (size_t)i * DI, nullptr);
        // selective scan + silu(z) gating -> g_y
        scan_kernel<<<BB * (DI / 16), 256>>>(A_log + (size_t)i * DI * NS, Dp + (size_t)i * DI);
        // h += y @ mo_W[i]^T      (8192 x 512 x 1024)
        sgemm_kernel<2><<<dim3(DC / BN, NROWS / BM), 256>>>(
            py, mo_W + (size_t)i * DC * DI, ph,
            NROWS, DC, DI, DI, DI, DC, nullptr, nullptr);
    }

    buildout_kernel<<<(NROWS * DM) / 256, 256>>>();
    // d_out = s + out @ po_W^T + po_b   (8192 x 1024 x 1024)
    sgemm_kernel<3><<<dim3(DM / BN, NROWS / BM), 256>>>(
        pout, po_W, (float*)d_out,
        NROWS, DM, DM, DM, DM, DM, po_b, ps);
}

// round 3
// speedup vs baseline: 1.1764x; 1.1764x over previous
#include <cuda_runtime.h>
#include <math.h>
#include <stdint.h>

// Problem constants
#define BB   4
#define LLEN 2048
#define DM   1024
#define DC   512
#define DI   1024
#define NS   16
#define DTRC 32
#define NROWS (BB*LLEN)   // 8192

// ---------------- scratch (module-load allocation, allowed) ----------------
__device__ float g_s    [NROWS*DM];
__device__ float g_h    [NROWS*DC];
__device__ float g_xn   [NROWS*DC];
__device__ float g_xz   [NROWS*2*DI];
__device__ float g_xc   [NROWS*DI];
__device__ float g_dbc  [NROWS*64];
__device__ float g_delta[NROWS*DI];
__device__ float g_y    [NROWS*DI];
__device__ float g_out  [NROWS*DM];

// ---------------- helpers ----------------
__device__ __forceinline__ float softplusf(float x) {
    return (x > 20.f) ? x : log1pf(expf(x));
}
__device__ __forceinline__ float siluf(float x) {
    return x / (1.f + __expf(-x));
}
__device__ __forceinline__ uint32_t to_tf32(float x) {
    uint32_t r;
    asm("cvt.rna.tf32.f32 %0, %1;" : "=r"(r) : "f"(x));
    return r;
}
__device__ __forceinline__ void mma_tf32(float& c0, float& c1, float& c2, float& c3,
                                         uint32_t a0, uint32_t a1, uint32_t a2, uint32_t a3,
                                         uint32_t b0, uint32_t b1) {
    asm volatile("mma.sync.aligned.m16n8k8.row.col.f32.tf32.tf32.f32 "
        "{%0,%1,%2,%3}, {%4,%5,%6,%7}, {%8,%9}, {%0,%1,%2,%3};"
        : "+f"(c0), "+f"(c1), "+f"(c2), "+f"(c3)
        : "r"(a0), "r"(a1), "r"(a2), "r"(a3), "r"(b0), "r"(b1));
}

// ---------------- LayerNorm: src -> g_s ; also init g_h = s[:, :512] ----------------
__global__ void layernorm_kernel(const float* __restrict__ src,
                                 const float* __restrict__ gma,
                                 const float* __restrict__ bta)
{
    int row = blockIdx.x;
    int t = threadIdx.x;
    const float4* x4 = (const float4*)(src + (size_t)row * DM);
    float4 v = x4[t];
    float sum = v.x + v.y + v.z + v.w;
    float sq  = v.x*v.x + v.y*v.y + v.z*v.z + v.w*v.w;
    #pragma unroll
    for (int o = 16; o > 0; o >>= 1) {
        sum += __shfl_down_sync(0xffffffffu, sum, o);
        sq  += __shfl_down_sync(0xffffffffu, sq,  o);
    }
    __shared__ float sm[18];
    int w = t >> 5;
    if ((t & 31) == 0) { sm[w] = sum; sm[8 + w] = sq; }
    __syncthreads();
    if (t == 0) {
        float s1 = 0.f, s2 = 0.f;
        #pragma unroll
        for (int i = 0; i < 8; i++) { s1 += sm[i]; s2 += sm[8 + i]; }
        float mu  = s1 * (1.f / DM);
        float var = s2 * (1.f / DM) - mu * mu;
        sm[16] = mu;
        sm[17] = rsqrtf(var + 1e-5f);
    }
    __syncthreads();
    float mu = sm[16], inv = sm[17];
    float4 gv = ((const float4*)gma)[t];
    float4 bv = ((const float4*)bta)[t];
    float4 o;
    o.x = (v.x - mu) * inv * gv.x + bv.x;
    o.y = (v.y - mu) * inv * gv.y + bv.y;
    o.z = (v.z - mu) * inv * gv.z + bv.z;
    o.w = (v.w - mu) * inv * gv.w + bv.w;
    ((float4*)(g_s + (size_t)row * DM))[t] = o;
    if (t < DC / 4) ((float4*)(g_h + (size_t)row * DC))[t] = o;
}

// ---------------- RMSNorm: g_h -> g_xn ----------------
__global__ void rmsnorm_kernel(const float* __restrict__ wptr)
{
    int row = blockIdx.x;
    int t = threadIdx.x;
    float4 v = ((const float4*)(g_h + (size_t)row * DC))[t];
    float sq = v.x*v.x + v.y*v.y + v.z*v.z + v.w*v.w;
    #pragma unroll
    for (int o = 16; o > 0; o >>= 1) sq += __shfl_down_sync(0xffffffffu, sq, o);
    __shared__ float sm[5];
    int w = t >> 5;
    if ((t & 31) == 0) sm[w] = sq;
    __syncthreads();
    if (t == 0) {
        float s2 = sm[0] + sm[1] + sm[2] + sm[3];
        sm[4] = rsqrtf(s2 * (1.f / DC) + 1e-5f);
    }
    __syncthreads();
    float inv = sm[4];
    float4 wv = ((const float4*)wptr)[t];
    float4 o;
    o.x = v.x * inv * wv.x;
    o.y = v.y * inv * wv.y;
    o.z = v.z * inv * wv.z;
    o.w = v.w * inv * wv.w;
    ((float4*)(g_xn + (size_t)row * DC))[t] = o;
}

// ---------------- TF32 tensor-core GEMM: C[M,N] = A[M,K] @ B[N,K]^T (+ epilogues) ----------------
// EPI 0: C = acc
// EPI 1: C = softplus(acc + bias[col])
// EPI 2: C += acc
// EPI 3: C = addsrc[row,col] + acc + bias[col]
//
// Tile: BM=128 x BN_ x BK=16. 256 threads = 8 warps, layout 4 (m) x 2 (n).
// Per-warp tile: 32 x (BN_/2), built from m16n8k8 MMAs.
// smem layouts As[k][m], Bs[k][n] padded to stride%32==8 words -> conflict-free frag loads.

#define TBM 128
#define TBK 16

template<int EPI, int BN_>
__global__ void __launch_bounds__(256)
tgemm_kernel(const float* __restrict__ A, const float* __restrict__ B,
             float* __restrict__ C, int M, int N, int K,
             int lda, int ldb, int ldc,
             const float* __restrict__ bias, const float* __restrict__ addsrc)
{
    constexpr int PAD = 8;                 // (128+8)%32==8, (64+8)%32==8
    constexpr int NT  = BN_ / 16;          // n8-tiles per warp (warp covers BN_/2)
    __shared__ uint32_t As[TBK][TBM + PAD];
    __shared__ uint32_t Bs[TBK][BN_ + PAD];

    const int tid  = threadIdx.x;
    const int lane = tid & 31;
    const int wid  = tid >> 5;
    const int warp_m = wid & 3;            // 0..3
    const int warp_n = wid >> 2;           // 0..1
    const int bm = blockIdx.y * TBM;
    const int bn = blockIdx.x * BN_;

    float c[2][NT][4];
    #pragma unroll
    for (int i = 0; i < 2; i++)
        #pragma unroll
        for (int j = 0; j < NT; j++)
            #pragma unroll
            for (int q = 0; q < 4; q++) c[i][j][q] = 0.f;

    // global->reg load mapping
    const int lm = tid >> 2;               // 0..63
    const int lk = (tid & 3) * 4;          // 0,4,8,12
    const float* Ap0 = A + (size_t)(bm + lm)      * lda + lk;
    const float* Ap1 = A + (size_t)(bm + lm + 64) * lda + lk;
    const float* Bp0 = B + (size_t)(bn + lm)      * ldb + lk;
    const float* Bp1 = (BN_ == 128) ? (B + (size_t)(bn + lm + 64) * ldb + lk) : Bp0;

    float4 ra0 = *(const float4*)(Ap0);
    float4 ra1 = *(const float4*)(Ap1);
    float4 rb0 = *(const float4*)(Bp0);
    float4 rb1;
    if (BN_ == 128) rb1 = *(const float4*)(Bp1);

    const int qrow = lane >> 2;            // 0..7
    const int qcol = lane & 3;             // 0..3

    for (int k0 = 0; k0 < K; k0 += TBK) {
        // stage regs -> smem (convert to tf32 here)
        As[lk + 0][lm] = to_tf32(ra0.x); As[lk + 1][lm] = to_tf32(ra0.y);
        As[lk + 2][lm] = to_tf32(ra0.z); As[lk + 3][lm] = to_tf32(ra0.w);
        As[lk + 0][lm + 64] = to_tf32(ra1.x); As[lk + 1][lm + 64] = to_tf32(ra1.y);
        As[lk + 2][lm + 64] = to_tf32(ra1.z); As[lk + 3][lm + 64] = to_tf32(ra1.w);
        Bs[lk + 0][lm] = to_tf32(rb0.x); Bs[lk + 1][lm] = to_tf32(rb0.y);
        Bs[lk + 2][lm] = to_tf32(rb0.z); Bs[lk + 3][lm] = to_tf32(rb0.w);
        if (BN_ == 128) {
            Bs[lk + 0][lm + 64] = to_tf32(rb1.x); Bs[lk + 1][lm + 64] = to_tf32(rb1.y);
            Bs[lk + 2][lm + 64] = to_tf32(rb1.z); Bs[lk + 3][lm + 64] = to_tf32(rb1.w);
        }
        __syncthreads();

        // prefetch next tile into regs (overlaps with MMA below)
        if (k0 + TBK < K) {
            ra0 = *(const float4*)(Ap0 + k0 + TBK);
            ra1 = *(const float4*)(Ap1 + k0 + TBK);
            rb0 = *(const float4*)(Bp0 + k0 + TBK);
            if (BN_ == 128) rb1 = *(const float4*)(Bp1 + k0 + TBK);
        }

        #pragma unroll
        for (int ks = 0; ks < TBK; ks += 8) {
            uint32_t af[2][4];
            #pragma unroll
            for (int mt = 0; mt < 2; mt++) {
                int r = warp_m * 32 + mt * 16 + qrow;
                af[mt][0] = As[ks + qcol    ][r];
                af[mt][1] = As[ks + qcol    ][r + 8];
                af[mt][2] = As[ks + qcol + 4][r];
                af[mt][3] = As[ks + qcol + 4][r + 8];
            }
            uint32_t bf[NT][2];
            #pragma unroll
            for (int nt = 0; nt < NT; nt++) {
                int n = warp_n * (BN_ / 2) + nt * 8 + qrow;
                bf[nt][0] = Bs[ks + qcol    ][n];
                bf[nt][1] = Bs[ks + qcol + 4][n];
            }
            #pragma unroll
            for (int mt = 0; mt < 2; mt++)
                #pragma unroll
                for (int nt = 0; nt < NT; nt++)
                    mma_tf32(c[mt][nt][0], c[mt][nt][1], c[mt][nt][2], c[mt][nt][3],
                             af[mt][0], af[mt][1], af[mt][2], af[mt][3],
                             bf[nt][0], bf[nt][1]);
        }
        __syncthreads();
    }

    // epilogue
    #pragma unroll
    for (int mt = 0; mt < 2; mt++) {
        int row0 = bm + warp_m * 32 + mt * 16 + qrow;
        #pragma unroll
        for (int nt = 0; nt < NT; nt++) {
            int col = bn + warp_n * (BN_ / 2) + nt * 8 + qcol * 2;
            #pragma unroll
            for (int half = 0; half < 2; half++) {
                int row = row0 + half * 8;
                size_t ci0 = (size_t)row * ldc + col;
                float v0 = c[mt][nt][half * 2 + 0];
                float v1 = c[mt][nt][half * 2 + 1];
                if (EPI == 0) {
                    C[ci0] = v0; C[ci0 + 1] = v1;
                } else if (EPI == 1) {
                    C[ci0]     = softplusf(v0 + bias[col]);
                    C[ci0 + 1] = softplusf(v1 + bias[col + 1]);
                } else if (EPI == 2) {
                    C[ci0] += v0; C[ci0 + 1] += v1;
                } else {
                    C[ci0]     = addsrc[ci0]     + v0 + bias[col];
                    C[ci0 + 1] = addsrc[ci0 + 1] + v1 + bias[col + 1];
                }
            }
        }
    }
}

// ---------------- depthwise causal conv (DCONV=4) + bias + silu ----------------
__global__ void conv_kernel(const float* __restrict__ cw, const float* __restrict__ cb)
{
    int idx = blockIdx.x * blockDim.x + threadIdx.x;
    if (idx >= NROWS * DI) return;
    int d   = idx & (DI - 1);
    int row = idx >> 10;
    int l   = row & (LLEN - 1);
    float w0 = cw[d * 4 + 0], w1 = cw[d * 4 + 1], w2 = cw[d * 4 + 2], w3 = cw[d * 4 + 3];
    float acc = cb[d];
    if (l >= 3) acc = fmaf(w0, g_xz[(size_t)(row - 3) * (2 * DI) + d], acc);
    if (l >= 2) acc = fmaf(w1, g_xz[(size_t)(row - 2) * (2 * DI) + d], acc);
    if (l >= 1) acc = fmaf(w2, g_xz[(size_t)(row - 1) * (2 * DI) + d], acc);
    acc = fmaf(w3, g_xz[(size_t)row * (2 * DI) + d], acc);
    g_xc[idx] = siluf(acc);
}

// ---------------- selective scan ----------------
__global__ void scan_kernel(const float* __restrict__ A_log, const float* __restrict__ Dp)
{
    int b     = blockIdx.x >> 6;
    int dbase = (blockIdx.x & 63) << 4;
    int warp  = threadIdx.x >> 5;
    int lane  = threadIdx.x & 31;
    int g     = lane >> 4;
    int n     = lane & 15;
    int d     = dbase + warp * 2 + g;

    float An  = -__expf(A_log[d * NS + n]);
    float Dpd = Dp[d];
    float h = 0.f;
    size_t rowBase = (size_t)b * LLEN;

    for (int l = 0; l < LLEN; l++) {
        size_t r = rowBase + l;
        float dv = g_delta[r * DI + d];
        float xv = g_xc[r * DI + d];
        float Bn = g_dbc[r * 64 + 32 + n];
        float Cn = g_dbc[r * 64 + 48 + n];
        float a  = __expf(dv * An);
        h = fmaf(a, h, dv * xv * Bn);
        float contrib = h * Cn;
        contrib += __shfl_xor_sync(0xffffffffu, contrib, 8);
        contrib += __shfl_xor_sync(0xffffffffu, contrib, 4);
        contrib += __shfl_xor_sync(0xffffffffu, contrib, 2);
        contrib += __shfl_xor_sync(0xffffffffu, contrib, 1);
        if (n == 0) {
            float zv = g_xz[r * (2 * DI) + DI + d];
            g_y[r * DI + d] = (contrib + Dpd * xv) * siluf(zv);
        }
    }
}

// ---------------- build out = concat(x1, x2 + h) ----------------
__global__ void buildout_kernel()
{
    int idx = blockIdx.x * blockDim.x + threadIdx.x;
    if (idx >= NROWS * DM) return;
    int c   = idx & (DM - 1);
    int row = idx >> 10;
    float v = g_s[idx];
    if (c >= DC) v += g_h[(size_t)row * DC + (c - DC)];
    g_out[idx] = v;
}

// ---------------- launch ----------------
extern "C" void kernel_launch(void* const* d_in, const int* in_sizes, int n_in,
                              void* d_out, int out_size)
{
    const float* src    = (const float*)d_in[0];
    const float* ln_g   = (const float*)d_in[1];
    const float* ln_b   = (const float*)d_in[2];
    const float* po_W   = (const float*)d_in[3];
    const float* po_b   = (const float*)d_in[4];
    const float* rms_w  = (const float*)d_in[5];
    const float* in_W   = (const float*)d_in[6];
    const float* conv_w = (const float*)d_in[7];
    const float* conv_b = (const float*)d_in[8];
    const float* xp_W   = (const float*)d_in[9];
    const float* dt_W   = (const float*)d_in[10];
    const float* dt_b   = (const float*)d_in[11];
    const float* A_log  = (const float*)d_in[12];
    const float* Dp     = (const float*)d_in[13];
    const float* mo_W   = (const float*)d_in[14];

    float *ps, *pxn, *pxz, *pxc, *pdbc, *pdelta, *py, *ph, *pout;
    cudaGetSymbolAddress((void**)&ps,     g_s);
    cudaGetSymbolAddress((void**)&ph,     g_h);
    cudaGetSymbolAddress((void**)&pxn,    g_xn);
    cudaGetSymbolAddress((void**)&pxz,    g_xz);
    cudaGetSymbolAddress((void**)&pxc,    g_xc);
    cudaGetSymbolAddress((void**)&pdbc,   g_dbc);
    cudaGetSymbolAddress((void**)&pdelta, g_delta);
    cudaGetSymbolAddress((void**)&py,     g_y);
    cudaGetSymbolAddress((void**)&pout,   g_out);

    layernorm_kernel<<<NROWS, 256>>>(src, ln_g, ln_b);

    for (int i = 0; i < 2; i++) {
        rmsnorm_kernel<<<NROWS, 128>>>(rms_w + i * DC);
        // xz = xn @ in_W[i]^T     (8192 x 2048 x 512)
        tgemm_kernel<0, 128><<<dim3((2 * DI) / 128, NROWS / TBM), 256>>>(
            pxn, in_W + (size_t)i * 2 * DI * DC, pxz,
            NROWS, 2 * DI, DC, DC, DC, 2 * DI, nullptr, nullptr);
        // depthwise conv + silu
        conv_kernel<<<(NROWS * DI) / 256, 256>>>(conv_w + (size_t)i * DI * 4, conv_b + (size_t)i * DI);
        // dbc = xc @ xp_W[i]^T    (8192 x 64 x 1024)
        tgemm_kernel<0, 64><<<dim3(1, NROWS / TBM), 256>>>(
            pxc, xp_W + (size_t)i * 64 * DI, pdbc,
            NROWS, 64, DI, DI, DI, 64, nullptr, nullptr);
        // delta = softplus(dt @ dt_W[i]^T + dt_b)   (8192 x 1024 x 32), dt = dbc[:, :32] (lda=64)
        tgemm_kernel<1, 128><<<dim3(DI / 128, NROWS / TBM), 256>>>(
            pdbc, dt_W + (size_t)i * DI * DTRC, pdelta,
            NROWS, DI, DTRC, 64, DTRC, DI, dt_b + (size_t)i * DI, nullptr);
        // selective scan + silu(z) gating -> g_y
        scan_kernel<<<BB * (DI / 16), 256>>>(A_log + (size_t)i * DI * NS, Dp + (size_t)i * DI);
        // h += y @ mo_W[i]^T      (8192 x 512 x 1024)
        tgemm_kernel<2, 128><<<dim3(DC / 128, NROWS / TBM), 256>>>(
            py, mo_W + (size_t)i * DC * DI, ph,
            NROWS, DC, DI, DI, DI, DC, nullptr, nullptr);
    }

    buildout_kernel<<<(NROWS * DM) / 256, 256>>>();
    // d_out = s + out @ po_W^T + po_b   (8192 x 1024 x 1024)
    tgemm_kernel<3, 128><<<dim3(DM / 128, NROWS / TBM), 256>>>(
        pout, po_W, (float*)d_out,
        NROWS, DM, DM, DM, DM, DM, po_b, ps);
}